// round 16
// baseline (speedup 1.0000x reference)
#include <cuda_runtime.h>
#include <math.h>

#define B_DIM 256
#define T_DIM 250
#define NS    500
#define HID   512
#define G3    1536   // 3*HID
#define NBLK  128    // persistent blocks (4 b-tiles x 32 j-tiles)
#define HP    516    // h_s row pitch (floats)

// ---------------- scratch (device globals; allocation-free) ----------------
__device__ float d_gi[(size_t)B_DIM * T_DIM * G3];       // 393 MB, reused per layer
__device__ float d_hseq0[(size_t)B_DIM * T_DIM * HID];   // 131 MB
__device__ float d_hseq1[(size_t)B_DIM * T_DIM * HID];   // 131 MB
__device__ float d_wih0T[NS * G3];
__device__ float d_whh0T[HID * G3];
__device__ float d_wih1T[HID * G3];
__device__ float d_whh1T[HID * G3];
__device__ float d_fcwT[HID * NS];

// persistent-kernel barrier state (gen is monotonic across launches/replays)
__device__ unsigned d_bar_count = 0;
__device__ unsigned d_bar_gen   = 0;

// ---------------- transpose: out[c*rows + r] = in[r*cols + c] ----------------
__global__ void transpose_kernel(const float* __restrict__ in, float* __restrict__ out,
                                 int rows, int cols) {
    __shared__ float tile[32][33];
    int x = blockIdx.x * 32 + threadIdx.x;
    int y = blockIdx.y * 32 + threadIdx.y;
    if (x < cols && y < rows) tile[threadIdx.y][threadIdx.x] = in[(size_t)y * cols + x];
    __syncthreads();
    int ox = blockIdx.y * 32 + threadIdx.x;
    int oy = blockIdx.x * 32 + threadIdx.y;
    if (ox < rows && oy < cols) out[(size_t)oy * rows + ox] = tile[threadIdx.x][threadIdx.y];
}

// ---------------- big GEMM with bias: C[M,N] = A[M,K] @ B[K,N] + bias[N] ----------------
__global__ void gemm_bias_kernel(const float* __restrict__ A, const float* __restrict__ B,
                                 const float* __restrict__ bias, float* __restrict__ C,
                                 int M, int N, int K) {
    __shared__ float As[16][128];
    __shared__ float Bs[16][128];
    const int tid = threadIdx.x;
    const int tx = tid & 15;
    const int ty = tid >> 4;
    const int bm = blockIdx.y * 128;
    const int bn = blockIdx.x * 128;
    float acc[8][8] = {};
    for (int k0 = 0; k0 < K; k0 += 16) {
#pragma unroll
        for (int i = 0; i < 8; i++) {
            int idx = tid + i * 256;
            int row = idx >> 4, kk = idx & 15;
            int gk = k0 + kk;
            As[kk][row] = (gk < K) ? A[(size_t)(bm + row) * K + gk] : 0.f;
        }
#pragma unroll
        for (int i = 0; i < 8; i++) {
            int idx = tid + i * 256;
            int kk = idx >> 7, col = idx & 127;
            int gk = k0 + kk;
            Bs[kk][col] = (gk < K) ? B[(size_t)gk * N + bn + col] : 0.f;
        }
        __syncthreads();
#pragma unroll
        for (int kk = 0; kk < 16; kk++) {
            float a[8], b[8];
            float4 a0 = *(const float4*)&As[kk][ty * 8];
            float4 a1 = *(const float4*)&As[kk][ty * 8 + 4];
            float4 b0 = *(const float4*)&Bs[kk][tx * 8];
            float4 b1 = *(const float4*)&Bs[kk][tx * 8 + 4];
            a[0]=a0.x; a[1]=a0.y; a[2]=a0.z; a[3]=a0.w; a[4]=a1.x; a[5]=a1.y; a[6]=a1.z; a[7]=a1.w;
            b[0]=b0.x; b[1]=b0.y; b[2]=b0.z; b[3]=b0.w; b[4]=b1.x; b[5]=b1.y; b[6]=b1.z; b[7]=b1.w;
#pragma unroll
            for (int i = 0; i < 8; i++)
#pragma unroll
                for (int j = 0; j < 8; j++) acc[i][j] += a[i] * b[j];
        }
        __syncthreads();
    }
#pragma unroll
    for (int i = 0; i < 8; i++) {
        size_t row = (size_t)(bm + ty * 8 + i);
#pragma unroll
        for (int j = 0; j < 8; j++) {
            int col = bn + tx * 8 + j;
            C[row * N + col] = acc[i][j] + bias[col];
        }
    }
}

// ---------------- persistent GRU layer kernel (vectorized smem) ----------------
// grid (32, 4): j0 = blockIdx.x*16 (16 hidden cols), b0 = blockIdx.y*64 (64 batch rows)
// 128 threads: tx = j offset (0..15), ty = batch group (0..7); thread rows = i*8 + ty.
// smem: w4 [128 k-quads][3 gates][16 j] of float4 (k in lanes)  = 98,304 B
//       h_s [64 rows][516 pitch] floats (full K staged per step) = 132,096 B
__global__ void __launch_bounds__(128, 1)
gru_layer_persistent(const float* __restrict__ gi,
                     const float* __restrict__ whhT,   // (HID, G3) k-major
                     const float* __restrict__ bhh,
                     float* __restrict__ hseq) {
    extern __shared__ float sm[];
    float4* w4 = (float4*)sm;            // 6144 float4
    float*  h_s = sm + 128 * 48 * 4;     // offset 24576 floats

    const int tid = threadIdx.x;
    const int tx = tid & 15;
    const int ty = tid >> 4;
    const int j0 = blockIdx.x * 16;
    const int b0 = blockIdx.y * 64;
    const int j  = j0 + tx;

    // pack weights: w4[kk4*48 + g*16 + jj] = {w[4kk4..4kk4+3][g*HID + j0+jj]}
    for (int idx = tid; idx < 128 * 48; idx += 128) {
        int kk4 = idx / 48, r = idx - kk4 * 48, g = r >> 4, jj = r & 15;
        const float* src = whhT + (size_t)(kk4 * 4) * G3 + g * HID + j0 + jj;
        float4 v;
        v.x = src[0];
        v.y = src[G3];
        v.z = src[2 * G3];
        v.w = src[3 * G3];
        w4[idx] = v;
    }
    const float b_r = bhh[j];
    const float b_z = bhh[HID + j];
    const float b_n = bhh[2 * HID + j];

    // generation base: read before this launch's first barrier can release
    unsigned base = d_bar_gen;
    __syncthreads();

    for (int t = 0; t < T_DIM; t++) {
        if (t > 0) {
            // all block threads finished prior-step epilogue writes (and h_s reads)
            __syncthreads();
            if (tid == 0) {
                __threadfence();
                unsigned a = atomicAdd(&d_bar_count, 1u);
                if (a == NBLK - 1) {
                    d_bar_count = 0;
                    __threadfence();
                    atomicAdd(&d_bar_gen, 1u);
                } else {
                    volatile unsigned* vg = &d_bar_gen;
                    unsigned target = base + (unsigned)t;
                    while (*vg < target) { }
                    __threadfence();
                }
            }
            __syncthreads();
        }

        // prefetch gi for this step (long-latency LDG, overlaps h staging)
        float gi_r[8], gi_z[8], gi_n[8];
#pragma unroll
        for (int i = 0; i < 8; i++) {
            const float* gir = gi + ((size_t)(b0 + i * 8 + ty) * T_DIM + t) * G3 + j;
            gi_r[i] = gir[0];
            gi_z[i] = gir[HID];
            gi_n[i] = gir[2 * HID];
        }

        float acc[8][3] = {};
        float ho[8];
#pragma unroll
        for (int i = 0; i < 8; i++) ho[i] = 0.f;

        if (t > 0) {
            // stage full 64 x 512 h(t-1) tile; thread loads float4 column tid of every row
#pragma unroll 4
            for (int w = 0; w < 64; w++) {
                float4 v = *(const float4*)&hseq[((size_t)(b0 + w) * T_DIM + (t - 1)) * HID + tid * 4];
                *(float4*)&h_s[w * HP + tid * 4] = v;
            }
            __syncthreads();
#pragma unroll
            for (int i = 0; i < 8; i++) ho[i] = h_s[(i * 8 + ty) * HP + j];

            // inner GEMM: per k-quad, 3 w-float4 + 8 h-float4 + 96 FFMA
#pragma unroll 2
            for (int k4 = 0; k4 < 128; k4++) {
                const float4* wp = w4 + k4 * 48 + tx;
                float4 w0 = wp[0];
                float4 w1 = wp[16];
                float4 w2 = wp[32];
#pragma unroll
                for (int i = 0; i < 8; i++) {
                    float4 av = *(const float4*)&h_s[(i * 8 + ty) * HP + k4 * 4];
                    acc[i][0] += av.x * w0.x + av.y * w0.y + av.z * w0.z + av.w * w0.w;
                    acc[i][1] += av.x * w1.x + av.y * w1.y + av.z * w1.z + av.w * w1.w;
                    acc[i][2] += av.x * w2.x + av.y * w2.y + av.z * w2.z + av.w * w2.w;
                }
            }
        }

        // fused gate epilogue + h write
#pragma unroll
        for (int i = 0; i < 8; i++) {
            int b = b0 + i * 8 + ty;
            float r = 1.f / (1.f + expf(-(gi_r[i] + acc[i][0] + b_r)));
            float z = 1.f / (1.f + expf(-(gi_z[i] + acc[i][1] + b_z)));
            float n = tanhf(gi_n[i] + r * (acc[i][2] + b_n));
            float hn = (1.f - z) * n + z * ho[i];
            hseq[((size_t)b * T_DIM + t) * HID + j] = hn;
        }
    }
}

// ---------------- head: FC + silu + softmax + 30x rebalance ----------------
__global__ void head_kernel(const float* __restrict__ hseq1,
                            const float* __restrict__ fcwT,   // (HID, NS)
                            const float* __restrict__ fcb,
                            float* __restrict__ out) {
    __shared__ float h[HID];
    __shared__ float red[HID];
    __shared__ float w[HID];
    const int b = blockIdx.x;
    const int tid = threadIdx.x;   // 512
    h[tid] = hseq1[((size_t)b * T_DIM + (T_DIM - 1)) * HID + tid];
    __syncthreads();
    float val = 0.f;
    if (tid < NS) {
        float acc = fcb[tid];
#pragma unroll 8
        for (int k = 0; k < HID; k++) acc += h[k] * fcwT[k * NS + tid];
        val = acc / (1.f + expf(-acc));  // silu
    }
    red[tid] = (tid < NS) ? val : -1e30f;
    __syncthreads();
    for (int s = 256; s > 0; s >>= 1) {
        if (tid < s) red[tid] = fmaxf(red[tid], red[tid + s]);
        __syncthreads();
    }
    float m = red[0];
    __syncthreads();
    float e = (tid < NS) ? expf(val - m) : 0.f;
    red[tid] = e;
    __syncthreads();
    for (int s = 256; s > 0; s >>= 1) {
        if (tid < s) red[tid] += red[tid + s];
        __syncthreads();
    }
    float denom = red[0];
    __syncthreads();
    w[tid] = e / denom;
    __syncthreads();
    for (int it = 0; it < 30; it++) {
        float wv = w[tid];
        float wc = fminf(fmaxf(wv, 0.f), 0.1f);
        float diff = (tid < NS) ? (wv - wc) : 0.f;
        float nom = (tid < NS && wc != 0.1f) ? wc : 0.f;
        red[tid] = diff;
        __syncthreads();
        for (int s = 256; s > 0; s >>= 1) {
            if (tid < s) red[tid] += red[tid + s];
            __syncthreads();
        }
        float leftover = red[0];
        __syncthreads();
        red[tid] = nom;
        __syncthreads();
        for (int s = 256; s > 0; s >>= 1) {
            if (tid < s) red[tid] += red[tid + s];
            __syncthreads();
        }
        float nsum = red[0];
        __syncthreads();
        if (tid < NS) w[tid] = wc + leftover * nom / nsum;
        __syncthreads();
    }
    if (tid < NS) out[(size_t)b * NS + tid] = w[tid];
}

// ---------------- launch ----------------
extern "C" void kernel_launch(void* const* d_in, const int* in_sizes, int n_in,
                              void* d_out, int out_size) {
    const float* x    = (const float*)d_in[0];
    const float* wih0 = (const float*)d_in[1];
    const float* whh0 = (const float*)d_in[2];
    const float* bih0 = (const float*)d_in[3];
    const float* bhh0 = (const float*)d_in[4];
    const float* wih1 = (const float*)d_in[5];
    const float* whh1 = (const float*)d_in[6];
    const float* bih1 = (const float*)d_in[7];
    const float* bhh1 = (const float*)d_in[8];
    const float* fcw  = (const float*)d_in[9];
    const float* fcb  = (const float*)d_in[10];
    float* out = (float*)d_out;

    float *gi, *hs0, *hs1, *wih0T, *whh0T, *wih1T, *whh1T, *fcwT;
    cudaGetSymbolAddress((void**)&gi,    d_gi);
    cudaGetSymbolAddress((void**)&hs0,   d_hseq0);
    cudaGetSymbolAddress((void**)&hs1,   d_hseq1);
    cudaGetSymbolAddress((void**)&wih0T, d_wih0T);
    cudaGetSymbolAddress((void**)&whh0T, d_whh0T);
    cudaGetSymbolAddress((void**)&wih1T, d_wih1T);
    cudaGetSymbolAddress((void**)&whh1T, d_whh1T);
    cudaGetSymbolAddress((void**)&fcwT,  d_fcwT);

    static int smem_set = 0;
    const int SMEM_BYTES = (128 * 48 * 4 + 64 * HP) * 4;  // 98,304 + 132,096 = 230,400 B
    if (!smem_set) {
        cudaFuncSetAttribute(gru_layer_persistent,
                             cudaFuncAttributeMaxDynamicSharedMemorySize, SMEM_BYTES);
        smem_set = 1;
    }

    dim3 tb(32, 32);
    transpose_kernel<<<dim3((NS  + 31) / 32, (G3 + 31) / 32), tb>>>(wih0, wih0T, G3, NS);
    transpose_kernel<<<dim3((HID + 31) / 32, (G3 + 31) / 32), tb>>>(whh0, whh0T, G3, HID);
    transpose_kernel<<<dim3((HID + 31) / 32, (G3 + 31) / 32), tb>>>(wih1, wih1T, G3, HID);
    transpose_kernel<<<dim3((HID + 31) / 32, (G3 + 31) / 32), tb>>>(whh1, whh1T, G3, HID);
    transpose_kernel<<<dim3((HID + 31) / 32, (NS + 31) / 32), tb>>>(fcw,  fcwT,  NS, HID);

    const int M = B_DIM * T_DIM;  // 64000
    dim3 ggrid(G3 / 128, M / 128);
    dim3 pgrid(HID / 16, B_DIM / 64);  // (32, 4) = 128 blocks

    // layer 0
    gemm_bias_kernel<<<ggrid, 256>>>(x, wih0T, bih0, gi, M, G3, NS);
    gru_layer_persistent<<<pgrid, 128, SMEM_BYTES>>>(gi, whh0T, bhh0, hs0);

    // layer 1
    gemm_bias_kernel<<<ggrid, 256>>>(hs0, wih1T, bih1, gi, M, G3, HID);
    gru_layer_persistent<<<pgrid, 128, SMEM_BYTES>>>(gi, whh1T, bhh1, hs1);

    head_kernel<<<B_DIM, HID>>>(hs1, fcwT, fcb, out);
}

// round 17
// speedup vs baseline: 1.0736x; 1.0736x over previous
#include <cuda_runtime.h>
#include <math.h>

#define B_DIM 256
#define T_DIM 250
#define NS    500
#define HID   512
#define G3    1536   // 3*HID
#define NBLK  128    // persistent blocks (4 b-tiles x 32 j-tiles)
#define HP    516    // h_s row pitch (floats)

// ---------------- scratch (device globals; allocation-free) ----------------
__device__ float d_gi[(size_t)B_DIM * T_DIM * G3];       // 393 MB, reused per layer
__device__ float d_hseq0[(size_t)B_DIM * T_DIM * HID];   // 131 MB
__device__ float d_hseq1[(size_t)B_DIM * T_DIM * HID];   // 131 MB
__device__ float d_wih0T[NS * G3];
__device__ float d_whh0T[HID * G3];
__device__ float d_wih1T[HID * G3];
__device__ float d_whh1T[HID * G3];
__device__ float d_fcwT[HID * NS];

// persistent-kernel barrier state (gen is monotonic across launches/replays)
__device__ unsigned d_bar_count = 0;
__device__ unsigned d_bar_gen   = 0;

// ---------------- transpose: out[c*rows + r] = in[r*cols + c] ----------------
__global__ void transpose_kernel(const float* __restrict__ in, float* __restrict__ out,
                                 int rows, int cols) {
    __shared__ float tile[32][33];
    int x = blockIdx.x * 32 + threadIdx.x;
    int y = blockIdx.y * 32 + threadIdx.y;
    if (x < cols && y < rows) tile[threadIdx.y][threadIdx.x] = in[(size_t)y * cols + x];
    __syncthreads();
    int ox = blockIdx.y * 32 + threadIdx.x;
    int oy = blockIdx.x * 32 + threadIdx.y;
    if (ox < rows && oy < cols) out[(size_t)oy * rows + ox] = tile[threadIdx.x][threadIdx.y];
}

// ---------------- big GEMM with bias: C[M,N] = A[M,K] @ B[K,N] + bias[N] ----------------
__global__ void gemm_bias_kernel(const float* __restrict__ A, const float* __restrict__ B,
                                 const float* __restrict__ bias, float* __restrict__ C,
                                 int M, int N, int K) {
    __shared__ float As[16][128];
    __shared__ float Bs[16][128];
    const int tid = threadIdx.x;
    const int tx = tid & 15;
    const int ty = tid >> 4;
    const int bm = blockIdx.y * 128;
    const int bn = blockIdx.x * 128;
    float acc[8][8] = {};
    for (int k0 = 0; k0 < K; k0 += 16) {
#pragma unroll
        for (int i = 0; i < 8; i++) {
            int idx = tid + i * 256;
            int row = idx >> 4, kk = idx & 15;
            int gk = k0 + kk;
            As[kk][row] = (gk < K) ? A[(size_t)(bm + row) * K + gk] : 0.f;
        }
#pragma unroll
        for (int i = 0; i < 8; i++) {
            int idx = tid + i * 256;
            int kk = idx >> 7, col = idx & 127;
            int gk = k0 + kk;
            Bs[kk][col] = (gk < K) ? B[(size_t)gk * N + bn + col] : 0.f;
        }
        __syncthreads();
#pragma unroll
        for (int kk = 0; kk < 16; kk++) {
            float a[8], b[8];
            float4 a0 = *(const float4*)&As[kk][ty * 8];
            float4 a1 = *(const float4*)&As[kk][ty * 8 + 4];
            float4 b0 = *(const float4*)&Bs[kk][tx * 8];
            float4 b1 = *(const float4*)&Bs[kk][tx * 8 + 4];
            a[0]=a0.x; a[1]=a0.y; a[2]=a0.z; a[3]=a0.w; a[4]=a1.x; a[5]=a1.y; a[6]=a1.z; a[7]=a1.w;
            b[0]=b0.x; b[1]=b0.y; b[2]=b0.z; b[3]=b0.w; b[4]=b1.x; b[5]=b1.y; b[6]=b1.z; b[7]=b1.w;
#pragma unroll
            for (int i = 0; i < 8; i++)
#pragma unroll
                for (int j = 0; j < 8; j++) acc[i][j] += a[i] * b[j];
        }
        __syncthreads();
    }
#pragma unroll
    for (int i = 0; i < 8; i++) {
        size_t row = (size_t)(bm + ty * 8 + i);
#pragma unroll
        for (int j = 0; j < 8; j++) {
            int col = bn + tx * 8 + j;
            C[row * N + col] = acc[i][j] + bias[col];
        }
    }
}

// ---------------- persistent GRU layer kernel (vectorized smem) ----------------
// grid (32, 4): j0 = blockIdx.x*16 (16 hidden cols), b0 = blockIdx.y*64 (64 batch rows)
// 128 threads: tx = j offset (0..15), ty = batch group (0..7); thread rows = i*8 + ty.
// smem: w4 [128 k-quads][3 gates][16 j] of float4 (k in lanes)  = 98,304 B
//       h_s [64 rows][516 pitch] floats (full K staged per step) = 132,096 B
__global__ void __launch_bounds__(128, 1)
gru_layer_persistent(const float* __restrict__ gi,
                     const float* __restrict__ whhT,   // (HID, G3) k-major
                     const float* __restrict__ bhh,
                     float* __restrict__ hseq) {
    extern __shared__ float sm[];
    float4* w4 = (float4*)sm;            // 6144 float4
    float*  h_s = sm + 128 * 48 * 4;     // offset 24576 floats

    const int tid = threadIdx.x;
    const int tx = tid & 15;
    const int ty = tid >> 4;
    const int j0 = blockIdx.x * 16;
    const int b0 = blockIdx.y * 64;
    const int j  = j0 + tx;

    // pack weights: w4[kk4*48 + g*16 + jj] = {w[4kk4..4kk4+3][g*HID + j0+jj]}
    for (int idx = tid; idx < 128 * 48; idx += 128) {
        int kk4 = idx / 48, r = idx - kk4 * 48, g = r >> 4, jj = r & 15;
        const float* src = whhT + (size_t)(kk4 * 4) * G3 + g * HID + j0 + jj;
        float4 v;
        v.x = src[0];
        v.y = src[G3];
        v.z = src[2 * G3];
        v.w = src[3 * G3];
        w4[idx] = v;
    }
    const float b_r = bhh[j];
    const float b_z = bhh[HID + j];
    const float b_n = bhh[2 * HID + j];

    // generation base: read before this launch's first barrier can release
    unsigned base = d_bar_gen;
    __syncthreads();

    for (int t = 0; t < T_DIM; t++) {
        if (t > 0) {
            // all block threads finished prior-step epilogue writes (and h_s reads)
            __syncthreads();
            if (tid == 0) {
                __threadfence();
                unsigned a = atomicAdd(&d_bar_count, 1u);
                if (a == NBLK - 1) {
                    d_bar_count = 0;
                    __threadfence();
                    atomicAdd(&d_bar_gen, 1u);
                } else {
                    volatile unsigned* vg = &d_bar_gen;
                    unsigned target = base + (unsigned)t;
                    while (*vg < target) { }
                    __threadfence();
                }
            }
            __syncthreads();
        }

        // prefetch gi for this step (long-latency LDG, overlaps h staging)
        float gi_r[8], gi_z[8], gi_n[8];
#pragma unroll
        for (int i = 0; i < 8; i++) {
            const float* gir = gi + ((size_t)(b0 + i * 8 + ty) * T_DIM + t) * G3 + j;
            gi_r[i] = gir[0];
            gi_z[i] = gir[HID];
            gi_n[i] = gir[2 * HID];
        }

        float acc[8][3] = {};
        float ho[8];
#pragma unroll
        for (int i = 0; i < 8; i++) ho[i] = 0.f;

        if (t > 0) {
            // stage full 64 x 512 h(t-1) tile; thread loads float4 column tid of every row
#pragma unroll 4
            for (int w = 0; w < 64; w++) {
                float4 v = *(const float4*)&hseq[((size_t)(b0 + w) * T_DIM + (t - 1)) * HID + tid * 4];
                *(float4*)&h_s[w * HP + tid * 4] = v;
            }
            __syncthreads();
#pragma unroll
            for (int i = 0; i < 8; i++) ho[i] = h_s[(i * 8 + ty) * HP + j];

            // inner GEMM: per k-quad, 3 w-float4 + 8 h-float4 + 96 FFMA
#pragma unroll 2
            for (int k4 = 0; k4 < 128; k4++) {
                const float4* wp = w4 + k4 * 48 + tx;
                float4 w0 = wp[0];
                float4 w1 = wp[16];
                float4 w2 = wp[32];
#pragma unroll
                for (int i = 0; i < 8; i++) {
                    float4 av = *(const float4*)&h_s[(i * 8 + ty) * HP + k4 * 4];
                    acc[i][0] += av.x * w0.x + av.y * w0.y + av.z * w0.z + av.w * w0.w;
                    acc[i][1] += av.x * w1.x + av.y * w1.y + av.z * w1.z + av.w * w1.w;
                    acc[i][2] += av.x * w2.x + av.y * w2.y + av.z * w2.z + av.w * w2.w;
                }
            }
        }

        // fused gate epilogue + h write
#pragma unroll
        for (int i = 0; i < 8; i++) {
            int b = b0 + i * 8 + ty;
            float r = 1.f / (1.f + expf(-(gi_r[i] + acc[i][0] + b_r)));
            float z = 1.f / (1.f + expf(-(gi_z[i] + acc[i][1] + b_z)));
            float n = tanhf(gi_n[i] + r * (acc[i][2] + b_n));
            float hn = (1.f - z) * n + z * ho[i];
            hseq[((size_t)b * T_DIM + t) * HID + j] = hn;
        }
    }
}

// ---------------- head: FC + silu + softmax + 30x rebalance ----------------
__global__ void head_kernel(const float* __restrict__ hseq1,
                            const float* __restrict__ fcwT,   // (HID, NS)
                            const float* __restrict__ fcb,
                            float* __restrict__ out) {
    __shared__ float h[HID];
    __shared__ float red[HID];
    __shared__ float w[HID];
    const int b = blockIdx.x;
    const int tid = threadIdx.x;   // 512
    h[tid] = hseq1[((size_t)b * T_DIM + (T_DIM - 1)) * HID + tid];
    __syncthreads();
    float val = 0.f;
    if (tid < NS) {
        float acc = fcb[tid];
#pragma unroll 8
        for (int k = 0; k < HID; k++) acc += h[k] * fcwT[k * NS + tid];
        val = acc / (1.f + expf(-acc));  // silu
    }
    red[tid] = (tid < NS) ? val : -1e30f;
    __syncthreads();
    for (int s = 256; s > 0; s >>= 1) {
        if (tid < s) red[tid] = fmaxf(red[tid], red[tid + s]);
        __syncthreads();
    }
    float m = red[0];
    __syncthreads();
    float e = (tid < NS) ? expf(val - m) : 0.f;
    red[tid] = e;
    __syncthreads();
    for (int s = 256; s > 0; s >>= 1) {
        if (tid < s) red[tid] += red[tid + s];
        __syncthreads();
    }
    float denom = red[0];
    __syncthreads();
    w[tid] = e / denom;
    __syncthreads();
    for (int it = 0; it < 30; it++) {
        float wv = w[tid];
        float wc = fminf(fmaxf(wv, 0.f), 0.1f);
        float diff = (tid < NS) ? (wv - wc) : 0.f;
        float nom = (tid < NS && wc != 0.1f) ? wc : 0.f;
        red[tid] = diff;
        __syncthreads();
        for (int s = 256; s > 0; s >>= 1) {
            if (tid < s) red[tid] += red[tid + s];
            __syncthreads();
        }
        float leftover = red[0];
        __syncthreads();
        red[tid] = nom;
        __syncthreads();
        for (int s = 256; s > 0; s >>= 1) {
            if (tid < s) red[tid] += red[tid + s];
            __syncthreads();
        }
        float nsum = red[0];
        __syncthreads();
        if (tid < NS) w[tid] = wc + leftover * nom / nsum;
        __syncthreads();
    }
    if (tid < NS) out[(size_t)b * NS + tid] = w[tid];
}

// ---------------- launch ----------------
extern "C" void kernel_launch(void* const* d_in, const int* in_sizes, int n_in,
                              void* d_out, int out_size) {
    const float* x    = (const float*)d_in[0];
    const float* wih0 = (const float*)d_in[1];
    const float* whh0 = (const float*)d_in[2];
    const float* bih0 = (const float*)d_in[3];
    const float* bhh0 = (const float*)d_in[4];
    const float* wih1 = (const float*)d_in[5];
    const float* whh1 = (const float*)d_in[6];
    const float* bih1 = (const float*)d_in[7];
    const float* bhh1 = (const float*)d_in[8];
    const float* fcw  = (const float*)d_in[9];
    const float* fcb  = (const float*)d_in[10];
    float* out = (float*)d_out;

    float *gi, *hs0, *hs1, *wih0T, *whh0T, *wih1T, *whh1T, *fcwT;
    cudaGetSymbolAddress((void**)&gi,    d_gi);
    cudaGetSymbolAddress((void**)&hs0,   d_hseq0);
    cudaGetSymbolAddress((void**)&hs1,   d_hseq1);
    cudaGetSymbolAddress((void**)&wih0T, d_wih0T);
    cudaGetSymbolAddress((void**)&whh0T, d_whh0T);
    cudaGetSymbolAddress((void**)&wih1T, d_wih1T);
    cudaGetSymbolAddress((void**)&whh1T, d_whh1T);
    cudaGetSymbolAddress((void**)&fcwT,  d_fcwT);

    static int smem_set = 0;
    const int SMEM_BYTES = (128 * 48 * 4 + 64 * HP) * 4;  // 98,304 + 132,096 = 230,400 B
    if (!smem_set) {
        cudaFuncSetAttribute(gru_layer_persistent,
                             cudaFuncAttributeMaxDynamicSharedMemorySize, SMEM_BYTES);
        smem_set = 1;
    }

    dim3 tb(32, 32);
    transpose_kernel<<<dim3((NS  + 31) / 32, (G3 + 31) / 32), tb>>>(wih0, wih0T, G3, NS);
    transpose_kernel<<<dim3((HID + 31) / 32, (G3 + 31) / 32), tb>>>(whh0, whh0T, G3, HID);
    transpose_kernel<<<dim3((HID + 31) / 32, (G3 + 31) / 32), tb>>>(wih1, wih1T, G3, HID);
    transpose_kernel<<<dim3((HID + 31) / 32, (G3 + 31) / 32), tb>>>(whh1, whh1T, G3, HID);
    transpose_kernel<<<dim3((HID + 31) / 32, (NS + 31) / 32), tb>>>(fcw,  fcwT,  NS, HID);

    const int M = B_DIM * T_DIM;  // 64000
    dim3 ggrid(G3 / 128, M / 128);
    dim3 pgrid(HID / 16, B_DIM / 64);  // (32, 4) = 128 blocks

    // layer 0
    gemm_bias_kernel<<<ggrid, 256>>>(x, wih0T, bih0, gi, M, G3, NS);
    gru_layer_persistent<<<pgrid, 128, SMEM_BYTES>>>(gi, whh0T, bhh0, hs0);

    // layer 1
    gemm_bias_kernel<<<ggrid, 256>>>(hs0, wih1T, bih1, gi, M, G3, HID);
    gru_layer_persistent<<<pgrid, 128, SMEM_BYTES>>>(gi, whh1T, bhh1, hs1);

    head_kernel<<<B_DIM, HID>>>(hs1, fcwT, fcb, out);
}